// round 6
// baseline (speedup 1.0000x reference)
#include <cuda_runtime.h>
#include <cuda_bf16.h>
#include <math.h>
#include <stdint.h>

#define Cn   256
#define Hn   128
#define Wn   128
#define Bn   2
#define HWn  (Hn*Wn)        // 16384
#define NPIX (Bn*HWn)       // 32768
#define NCn  80
#define Kdcn 2304
#define WSZ  (Cn*Kdcn)      // 589824
#define NCHUNK 72           // 2304/32
#define NELEM (Bn*Cn*HWn)   // 8388608

// ---- smem layout (bytes) ----
// A: 256 oc x 32 k bf16, row pitch 80B  -> 20480 per plane
// B: 32 k x 128 px bf16, row pitch 272B ->  8704 per plane
#define A_HI 0
#define A_LO 20480
#define B_HI 40960
#define B_LO 49664
#define STAGE_SZ 58368
#define META (2*STAGE_SZ)           // 116736
#define SM_TOTAL (META + 9*128*32)  // +36864 = 153600

__device__ __forceinline__ uint32_t smem_to_u32(const void* p) {
    uint32_t a;
    asm("{ .reg .u64 t; cvta.to.shared.u64 t, %1; cvt.u32.u64 %0, t; }" : "=r"(a) : "l"(p));
    return a;
}
__device__ __forceinline__ void ldsm4(uint32_t r[4], uint32_t addr) {
    asm volatile("ldmatrix.sync.aligned.m8n8.x4.shared.b16 {%0,%1,%2,%3}, [%4];"
        : "=r"(r[0]), "=r"(r[1]), "=r"(r[2]), "=r"(r[3]) : "r"(addr));
}
__device__ __forceinline__ void ldsm4t(uint32_t r[4], uint32_t addr) {
    asm volatile("ldmatrix.sync.aligned.m8n8.x4.trans.shared.b16 {%0,%1,%2,%3}, [%4];"
        : "=r"(r[0]), "=r"(r[1]), "=r"(r[2]), "=r"(r[3]) : "r"(addr));
}
__device__ __forceinline__ void mma16816(float d[4], const uint32_t a[4],
                                         uint32_t b0, uint32_t b1) {
    asm volatile(
        "mma.sync.aligned.m16n8k16.row.col.f32.bf16.bf16.f32 "
        "{%0,%1,%2,%3}, {%4,%5,%6,%7}, {%8,%9}, {%0,%1,%2,%3};"
        : "+f"(d[0]), "+f"(d[1]), "+f"(d[2]), "+f"(d[3])
        : "r"(a[0]), "r"(a[1]), "r"(a[2]), "r"(a[3]), "r"(b0), "r"(b1));
}
__device__ __forceinline__ uint32_t prmt(uint32_t a, uint32_t b, uint32_t sel) {
    uint32_t d; asm("prmt.b32 %0,%1,%2,%3;" : "=r"(d) : "r"(a), "r"(b), "r"(sel));
    return d;
}
// packed pair: low16 = bf16 hi, high16 = bf16 lo (residual)
__device__ __forceinline__ uint32_t packpair(float v) {
    __nv_bfloat16 h = __float2bfloat16(v);
    float hf = __bfloat162float(h);
    __nv_bfloat16 l = __float2bfloat16(v - hf);
    uint16_t hb = *reinterpret_cast<uint16_t*>(&h);
    uint16_t lb = *reinterpret_cast<uint16_t*>(&l);
    return (uint32_t)hb | ((uint32_t)lb << 16);
}

// ---------------- scratch ----------------
__device__ uint32_t g_pkX [NELEM];
__device__ uint32_t g_pkA [NELEM];
__device__ uint32_t g_pkB [NELEM];
__device__ uint32_t g_ptspk[NELEM];
__device__ float g_cls [NELEM];
__device__ float g_pts [NELEM];
__device__ float g_bufA[NELEM];
__device__ float g_off [Bn*27*HWn];
__device__ float g_dcn [(size_t)Cn*NPIX];
__device__ __align__(16) __nv_bfloat16 g_whi[9*WSZ];
__device__ __align__(16) __nv_bfloat16 g_wlo[9*WSZ];

// ---------------- weight split: OIHW fp32 -> [oc][tap*256+ic] bf16 hi/lo ----------------
__global__ void __launch_bounds__(256)
split_w_kernel(const float* __restrict__ w, __nv_bfloat16* __restrict__ hi,
               __nv_bfloat16* __restrict__ lo)
{
    int idx = blockIdx.x * 256 + threadIdx.x;   // < 589824
    int oc = idx / Kdcn, kp = idx - oc * Kdcn;
    int tap = kp >> 8, ic = kp & 255;
    float v = w[((size_t)oc*256 + ic)*9 + tap];
    __nv_bfloat16 h = __float2bfloat16(v);
    hi[idx] = h;
    lo[idx] = __float2bfloat16(v - __bfloat162float(h));
}

// ---------------- pack x: fp32 -> packed pair ----------------
__global__ void __launch_bounds__(256)
pack_kernel(const float* __restrict__ in, uint32_t* __restrict__ out)
{
    int idx = blockIdx.x * 256 + threadIdx.x;
    float4 v = *reinterpret_cast<const float4*>(in + (size_t)idx*4);
    uint4 w = { packpair(v.x), packpair(v.y), packpair(v.z), packpair(v.w) };
    *reinterpret_cast<uint4*>(out + (size_t)idx*4) = w;
}

// =====================================================================
// Fused implicit-GEMM: D[256 oc][128 px] per CTA, K = 2304 tap-major.
// mode 0: conv3x3 pad1, input packed planes; bias+relu
// mode 1: dcn with mask (fp32 feat, bilinear); relu
// mode 2: dcn no mask; relu
// 512 threads = 16 warps (4m x 4n); warp tile 64 oc x 32 px.
// =====================================================================
__global__ void __launch_bounds__(512, 1)
gemm_kernel(int mode,
            const uint32_t* __restrict__ pkfeat,   // mode 0
            const float* __restrict__ feat,        // modes 1,2
            const __nv_bfloat16* __restrict__ whi, const __nv_bfloat16* __restrict__ wlo,
            const float* __restrict__ bias, const float* __restrict__ off,
            float* __restrict__ outf, uint32_t* __restrict__ outp)
{
    extern __shared__ __align__(128) char smem[];
    const uint32_t sbase = smem_to_u32(smem);
    const int tid  = threadIdx.x;
    const int wid  = tid >> 5, lane = tid & 31;
    const int nblk = blockIdx.x;
    const int b = nblk >> 7, y = nblk & 127;

    const int wm = wid & 3;        // 4 m-warps (64 oc each)
    const int wn = wid >> 2;       // 4 n-warps (32 px each)

    // ldmatrix lane offsets
    const int aR = (lane & 7) + ((lane >> 3) & 1) * 8;
    const int aC = (lane >> 4) * 8;
    const int bR = lane & 15;
    const int bC = (lane >> 4) * 8;

    // ---- dcn metadata precompute: bilinear weights+indices per (tap, px) ----
    if (mode != 0) {
        for (int e = tid; e < 9*128; e += 512) {
            int tap = e >> 7, p = e & 127;
            int ky = tap / 3 - 1, kx = tap % 3 - 1;
            int hw = y * Wn + p;
            const float* offb = off + (size_t)b*27*HWn + hw;
            float offy = __ldg(offb + (size_t)(2*tap)*HWn);
            float offx = __ldg(offb + (size_t)(2*tap + 1)*HWn);
            float py = (float)(y + ky) + offy;
            float px = (float)(p + kx) + offx;
            float fy0 = floorf(py), fx0 = floorf(px);
            float ly = py - fy0, lx = px - fx0;
            bool vy0 = (fy0 >= 0.f)       && (fy0 <= 127.f);
            bool vy1 = (fy0 + 1.f >= 0.f) && (fy0 + 1.f <= 127.f);
            bool vx0 = (fx0 >= 0.f)       && (fx0 <= 127.f);
            bool vx1 = (fx0 + 1.f >= 0.f) && (fx0 + 1.f <= 127.f);
            float w00 = (1.f-ly)*(1.f-lx) * ((vy0 && vx0) ? 1.f : 0.f);
            float w01 = (1.f-ly)*lx       * ((vy0 && vx1) ? 1.f : 0.f);
            float w10 = ly*(1.f-lx)       * ((vy1 && vx0) ? 1.f : 0.f);
            float w11 = ly*lx             * ((vy1 && vx1) ? 1.f : 0.f);
            if (mode == 1) {
                float m = __ldg(offb + (size_t)(18 + tap)*HWn);
                w00 *= m; w01 *= m; w10 *= m; w11 *= m;
            }
            int iy0 = min(max((int)fy0,     0), Hn-1);
            int iy1 = min(max((int)fy0 + 1, 0), Hn-1);
            int ix0 = min(max((int)fx0,     0), Wn-1);
            int ix1 = min(max((int)fx0 + 1, 0), Wn-1);
            char* mb = smem + META + e*32;
            *reinterpret_cast<float4*>(mb) = make_float4(w00, w01, w10, w11);
            *reinterpret_cast<int4*>(mb + 16) =
                make_int4(iy0*Wn + ix0, iy0*Wn + ix1, iy1*Wn + ix0, iy1*Wn + ix1);
        }
        __syncthreads();
    }

    float acc[16][4];
    #pragma unroll
    for (int i = 0; i < 16; i++)
        #pragma unroll
        for (int j = 0; j < 4; j++) acc[i][j] = 0.f;

    // ---------------- loader ----------------
    auto load_chunk = [&](int stg, int cc) {
        char* s = smem + stg * STAGE_SZ;
        // A: 256 oc x 32 k, hi+lo. thread: row=tid>>1, seg=tid&1 (16 bf16 = 32B)
        {
            int row = tid >> 1, seg = tid & 1;
            size_t gi = (size_t)row * Kdcn + cc * 32 + seg * 16;
            uint4 h0 = *reinterpret_cast<const uint4*>(whi + gi);
            uint4 h1 = *reinterpret_cast<const uint4*>(whi + gi + 8);
            uint4 l0 = *reinterpret_cast<const uint4*>(wlo + gi);
            uint4 l1 = *reinterpret_cast<const uint4*>(wlo + gi + 8);
            uint32_t so = (uint32_t)(row * 80 + seg * 32);
            *reinterpret_cast<uint4*>(s + A_HI + so)      = h0;
            *reinterpret_cast<uint4*>(s + A_HI + so + 16) = h1;
            *reinterpret_cast<uint4*>(s + A_LO + so)      = l0;
            *reinterpret_cast<uint4*>(s + A_LO + so + 16) = l1;
        }
        const int tap = cc >> 3;
        const int ic0 = (cc & 7) * 32;
        const int ky = tap / 3 - 1, kx = tap % 3 - 1;

        if (mode == 0) {
            // B from packed planes: 32 k-rows x 128 px; thread does 2 quads of 4 px
            int yy = y + ky;
            bool yok = (yy >= 0 && yy < Hn);
            #pragma unroll
            for (int i = 0; i < 2; i++) {
                int idx = i * 512 + tid;          // 0..1023
                int k   = idx >> 5;               // 0..31
                int px0 = (idx & 31) * 4;
                const uint32_t* src = pkfeat + ((size_t)(b*Cn + ic0 + k))*HWn + yy*Wn;
                uint32_t w0 = 0, w1 = 0, w2 = 0, w3 = 0;
                if (yok) {
                    int x0 = px0 + kx;
                    // interior fast path: all four in range unless at row edges
                    if (x0 >= 0 && x0 + 3 < Wn) {
                        w0 = __ldg(src + x0); w1 = __ldg(src + x0 + 1);
                        w2 = __ldg(src + x0 + 2); w3 = __ldg(src + x0 + 3);
                    } else {
                        if (x0 >= 0 && x0 < Wn)         w0 = __ldg(src + x0);
                        if (x0+1 >= 0 && x0+1 < Wn)     w1 = __ldg(src + x0 + 1);
                        if (x0+2 >= 0 && x0+2 < Wn)     w2 = __ldg(src + x0 + 2);
                        if (x0+3 >= 0 && x0+3 < Wn)     w3 = __ldg(src + x0 + 3);
                    }
                }
                uint2 hv = { prmt(w0, w1, 0x5410), prmt(w2, w3, 0x5410) };
                uint2 lv = { prmt(w0, w1, 0x7632), prmt(w2, w3, 0x7632) };
                uint32_t so = (uint32_t)(k * 272 + px0 * 2);
                *reinterpret_cast<uint2*>(s + B_HI + so) = hv;
                *reinterpret_cast<uint2*>(s + B_LO + so) = lv;
            }
        } else {
            // B via bilinear gather: thread = (pixel p, channel-group g of 8)
            int p = tid & 127, g = tid >> 7;
            const char* mb = smem + META + (tap*128 + p)*32;
            float4 wv = *reinterpret_cast<const float4*>(mb);
            int4  iv = *reinterpret_cast<const int4*>(mb + 16);
            const float* fb = feat + ((size_t)(b*Cn + ic0 + g*8))*HWn;
            #pragma unroll
            for (int j = 0; j < 8; j++) {
                const float* f = fb + (size_t)j*HWn;
                float v = wv.x*__ldg(f + iv.x) + wv.y*__ldg(f + iv.y)
                        + wv.z*__ldg(f + iv.z) + wv.w*__ldg(f + iv.w);
                __nv_bfloat16 h = __float2bfloat16(v);
                __nv_bfloat16 l = __float2bfloat16(v - __bfloat162float(h));
                int k = g*8 + j;
                *reinterpret_cast<__nv_bfloat16*>(s + B_HI + k*272 + p*2) = h;
                *reinterpret_cast<__nv_bfloat16*>(s + B_LO + k*272 + p*2) = l;
            }
        }
    };

    // ---------------- compute ----------------
    auto compute = [&](int stg) {
        uint32_t sa_hi = sbase + stg*STAGE_SZ + A_HI + (uint32_t)(((wm*64 + aR)*80 + aC*2));
        uint32_t sa_lo = sa_hi + (A_LO - A_HI);
        uint32_t sb_hi = sbase + stg*STAGE_SZ + B_HI + (uint32_t)((bR*272 + (wn*32 + bC)*2));
        uint32_t sb_lo = sb_hi + (B_LO - B_HI);
        #pragma unroll
        for (int s2 = 0; s2 < 2; s2++) {
            uint32_t bh[2][4], bl[2][4];
            ldsm4t(bh[0], sb_hi + s2*16*272);
            ldsm4t(bh[1], sb_hi + s2*16*272 + 32);
            ldsm4t(bl[0], sb_lo + s2*16*272);
            ldsm4t(bl[1], sb_lo + s2*16*272 + 32);
            #pragma unroll
            for (int mf = 0; mf < 4; mf++) {
                uint32_t ah[4], al[4];
                ldsm4(ah, sa_hi + mf*16*80 + s2*32);
                ldsm4(al, sa_lo + mf*16*80 + s2*32);
                #pragma unroll
                for (int q = 0; q < 4; q++) {
                    uint32_t b0h = bh[q>>1][(q&1)*2], b1h = bh[q>>1][(q&1)*2+1];
                    uint32_t b0l = bl[q>>1][(q&1)*2], b1l = bl[q>>1][(q&1)*2+1];
                    mma16816(acc[mf*4+q], ah, b0h, b1h);
                    mma16816(acc[mf*4+q], ah, b0l, b1l);
                    mma16816(acc[mf*4+q], al, b0h, b1h);
                }
            }
        }
    };

    // ---------------- pipelined main loop ----------------
    load_chunk(0, 0);
    __syncthreads();
    for (int c = 0; c < NCHUNK; c++) {
        int cur = c & 1;
        if (c + 1 < NCHUNK) load_chunk(cur ^ 1, c + 1);
        compute(cur);
        __syncthreads();
    }

    // ---------------- epilogue ----------------
    const int r  = lane >> 2;
    const int c2 = (lane & 3) * 2;
    #pragma unroll
    for (int mf = 0; mf < 4; mf++) {
        #pragma unroll
        for (int rr = 0; rr < 2; rr++) {
            int oc = wm*64 + mf*16 + r + rr*8;
            float bv = (mode == 0) ? __ldg(&bias[oc]) : 0.f;
            size_t base;
            if (mode == 0) base = ((size_t)(b*Cn + oc))*HWn + y*Wn;
            else           base = (size_t)oc*NPIX + (size_t)b*HWn + y*Wn;
            #pragma unroll
            for (int q = 0; q < 4; q++) {
                int x = wn*32 + q*8 + c2;
                float v0 = fmaxf(acc[mf*4+q][rr*2]   + bv, 0.f);
                float v1 = fmaxf(acc[mf*4+q][rr*2+1] + bv, 0.f);
                if (outf) {
                    float2 fv = { v0, v1 };
                    *reinterpret_cast<float2*>(outf + base + x) = fv;
                }
                if (outp) {
                    uint2 pv = { packpair(v0), packpair(v1) };
                    *reinterpret_cast<uint2*>(outp + base + x) = pv;
                }
            }
        }
    }
}

// ---------------- small kernels ----------------
__global__ void __launch_bounds__(256)
conv1x1_27_kernel(const float* __restrict__ in, const float* __restrict__ wgt,
                  const float* __restrict__ bias, float* __restrict__ out)
{
    __shared__ float ws[Cn*27];
    for (int idx = threadIdx.x; idx < Cn*27; idx += 256) {
        int o = idx >> 8, ic = idx & 255;
        ws[ic*27 + o] = wgt[(size_t)o*Cn + ic];
    }
    __syncthreads();
    int p  = blockIdx.x * 256 + threadIdx.x;
    int b  = p >> 14;
    int hw = p & (HWn - 1);
    float acc[27];
    #pragma unroll
    for (int o = 0; o < 27; o++) acc[o] = 0.f;
    const float* ip = in + (size_t)b*Cn*HWn + hw;
    for (int ic = 0; ic < Cn; ic++) {
        float v = __ldg(ip + (size_t)ic*HWn);
        #pragma unroll
        for (int o = 0; o < 27; o++) acc[o] += v * ws[ic*27 + o];
    }
    #pragma unroll
    for (int o = 0; o < 27; o++)
        out[((size_t)(b*27) + o)*HWn + hw] = acc[o] + bias[o];
}

__global__ void __launch_bounds__(256)
conv1x1_cls_kernel(const float* __restrict__ in, const float* __restrict__ wgt,
                   const float* __restrict__ bias, float* __restrict__ out)
{
    __shared__ float ws[Cn*16];
    int g = blockIdx.y;
    for (int idx = threadIdx.x; idx < Cn*16; idx += 256) {
        int j = idx >> 8, ic = idx & 255;
        ws[ic*16 + j] = wgt[(size_t)(g*16 + j)*Cn + ic];
    }
    __syncthreads();
    int p  = blockIdx.x * 256 + threadIdx.x;
    int b  = p >> 14;
    int hw = p & (HWn - 1);
    float acc[16];
    #pragma unroll
    for (int j = 0; j < 16; j++) acc[j] = 0.f;
    for (int ic = 0; ic < Cn; ic++) {
        float v = __ldg(&in[(size_t)ic*NPIX + p]);
        #pragma unroll
        for (int j = 0; j < 16; j++) acc[j] += v * ws[ic*16 + j];
    }
    #pragma unroll
    for (int j = 0; j < 16; j++) {
        int oc = g*16 + j;
        out[((size_t)(b*NCn) + oc)*HWn + hw] = acc[j] + bias[oc];
    }
}

__global__ void __launch_bounds__(256)
ref_fused_kernel(const float* __restrict__ in, const float* __restrict__ wgt,
                 const float* __restrict__ bias, const float* __restrict__ off,
                 float* __restrict__ dout)
{
    __shared__ float ws[Cn*18];
    for (int idx = threadIdx.x; idx < Cn*18; idx += 256) {
        int o = idx >> 8, ic = idx & 255;
        ws[ic*18 + o] = wgt[(size_t)o*Cn + ic];
    }
    __syncthreads();
    int p  = blockIdx.x * 256 + threadIdx.x;
    int b  = p >> 14;
    int hw = p & (HWn - 1);
    float acc[18];
    #pragma unroll
    for (int o = 0; o < 18; o++) acc[o] = 0.f;
    for (int ic = 0; ic < Cn; ic++) {
        float v = __ldg(&in[(size_t)ic*NPIX + p]);
        #pragma unroll
        for (int o = 0; o < 18; o++) acc[o] += v * ws[ic*18 + o];
    }
    float refine[18];
    #pragma unroll
    for (int o = 0; o < 18; o++)
        refine[o] = acc[o] + bias[o] + off[((size_t)(b*27) + o)*HWn + hw];
    float m0 = 0.f, m1 = 0.f;
    #pragma unroll
    for (int q = 0; q < 9; q++) { m0 += refine[2*q]; m1 += refine[2*q + 1]; }
    m0 *= (1.f/9.f); m1 *= (1.f/9.f);
    float wh0 = 0.f, wh1 = 0.f;
    #pragma unroll
    for (int q = 0; q < 9; q++) {
        wh0 = fmaxf(wh0, fabsf(refine[2*q]     + m0));
        wh1 = fmaxf(wh1, fabsf(refine[2*q + 1] + m1));
    }
    const size_t OUT_WH  = (size_t)Bn*NCn*HWn;
    const size_t OUT_REG = OUT_WH + (size_t)Bn*2*HWn;
    dout[OUT_WH  + ((size_t)(b*2) + 0)*HWn + hw] = wh0;
    dout[OUT_WH  + ((size_t)(b*2) + 1)*HWn + hw] = wh1;
    dout[OUT_REG + ((size_t)(b*2) + 0)*HWn + hw] = m0;
    dout[OUT_REG + ((size_t)(b*2) + 1)*HWn + hw] = m1;
}

// =====================================================================
extern "C" void kernel_launch(void* const* d_in, const int* in_sizes, int n_in,
                              void* d_out, int out_size)
{
    const float* x           = (const float*)d_in[0];
    const float* wconv[9]    = { (const float*)d_in[1],  (const float*)d_in[5],
                                 (const float*)d_in[9],  (const float*)d_in[3],
                                 (const float*)d_in[7],  (const float*)d_in[11],
                                 (const float*)d_in[13], (const float*)d_in[17],
                                 (const float*)d_in[20] };
    const float* cls_b0      = (const float*)d_in[2];
    const float* cls_b1      = (const float*)d_in[6];
    const float* cls_b2      = (const float*)d_in[10];
    const float* reg_b0      = (const float*)d_in[4];
    const float* reg_b1      = (const float*)d_in[8];
    const float* reg_b2      = (const float*)d_in[12];
    const float* init_conv_b = (const float*)d_in[14];
    const float* init_out_w  = (const float*)d_in[15];
    const float* init_out_b  = (const float*)d_in[16];
    const float* cls_out_w   = (const float*)d_in[18];
    const float* cls_out_b   = (const float*)d_in[19];
    const float* ref_out_w   = (const float*)d_in[21];
    const float* ref_out_b   = (const float*)d_in[22];
    float* out = (float*)d_out;

    uint32_t *pkX, *pkA, *pkB, *ptspk;
    float *cls, *pts, *bufA, *off, *dcn;
    __nv_bfloat16 *whi, *wlo;
    cudaGetSymbolAddress((void**)&pkX,  g_pkX);
    cudaGetSymbolAddress((void**)&pkA,  g_pkA);
    cudaGetSymbolAddress((void**)&pkB,  g_pkB);
    cudaGetSymbolAddress((void**)&ptspk,g_ptspk);
    cudaGetSymbolAddress((void**)&cls,  g_cls);
    cudaGetSymbolAddress((void**)&pts,  g_pts);
    cudaGetSymbolAddress((void**)&bufA, g_bufA);
    cudaGetSymbolAddress((void**)&off,  g_off);
    cudaGetSymbolAddress((void**)&dcn,  g_dcn);
    cudaGetSymbolAddress((void**)&whi,  g_whi);
    cudaGetSymbolAddress((void**)&wlo,  g_wlo);

    cudaFuncSetAttribute(gemm_kernel, cudaFuncAttributeMaxDynamicSharedMemorySize, SM_TOTAL);

    #define SPLIT(l) split_w_kernel<<<Kdcn, 256>>>(wconv[l], whi + (size_t)(l)*WSZ, wlo + (size_t)(l)*WSZ)
    #define GEMM(md, pk_, f_, l, bias_, off_, of_, op_) \
        gemm_kernel<<<256, 512, SM_TOTAL>>>(md, pk_, f_, whi + (size_t)(l)*WSZ, \
                                            wlo + (size_t)(l)*WSZ, bias_, off_, of_, op_)

    // launch order arranged so launch #6 (0-indexed 5) is the first gemm_kernel (ncu -s 5 -c 1)
    pack_kernel<<<NELEM/1024, 256>>>(x, pkX);            // 1
    SPLIT(0); SPLIT(1); SPLIT(2); SPLIT(3);              // 2-5
    // cls tower
    GEMM(0, pkX, nullptr, 0, cls_b0, nullptr, nullptr, pkA);   // 6 <- profiled
    SPLIT(4); SPLIT(5); SPLIT(6); SPLIT(7); SPLIT(8);
    GEMM(0, pkA, nullptr, 1, cls_b1, nullptr, nullptr, pkB);
    GEMM(0, pkB, nullptr, 2, cls_b2, nullptr, cls, nullptr);
    // reg tower
    GEMM(0, pkX, nullptr, 3, reg_b0, nullptr, nullptr, pkA);
    GEMM(0, pkA, nullptr, 4, reg_b1, nullptr, nullptr, pkB);
    GEMM(0, pkB, nullptr, 5, reg_b2, nullptr, pts, ptspk);
    // init branch
    GEMM(0, ptspk, nullptr, 6, init_conv_b, nullptr, bufA, nullptr);
    conv1x1_27_kernel<<<128, 256>>>(bufA, init_out_w, init_out_b, off);

    // cls dcn (mask) -> cls head
    GEMM(1, nullptr, cls, 7, nullptr, off, dcn, nullptr);
    conv1x1_cls_kernel<<<dim3(128, 5), 256>>>(dcn, cls_out_w, cls_out_b, out);

    // ref dcn (no mask) -> fused refine/wh/reg
    GEMM(2, nullptr, pts, 8, nullptr, off, dcn, nullptr);
    ref_fused_kernel<<<128, 256>>>(dcn, ref_out_w, ref_out_b, off, out);
}